// round 1
// baseline (speedup 1.0000x reference)
#include <cuda_runtime.h>
#include <math.h>

#define B_   2
#define S_   2048
#define NH   16
#define DK   64
#define HID  1024
#define ROWS (B_ * S_)          // 4096

static const size_t OUT_ELEMS = (size_t)B_ * S_ * HID;   // 4,194,304

// Scratch (allocation-free rule: __device__ globals)
__device__ float g_Q[(size_t)ROWS * HID];
__device__ float g_K[(size_t)ROWS * HID];
__device__ float g_V[(size_t)ROWS * HID];
__device__ float g_ctx[(size_t)ROWS * HID];
__device__ float g_tmp[(size_t)ROWS * HID];

// ---------------------------------------------------------------------------
// Block reductions (256 threads = 8 warps)
// ---------------------------------------------------------------------------
__device__ __forceinline__ float blockReduceMax(float v) {
    __shared__ float s[8];
    const int lane = threadIdx.x & 31, wid = threadIdx.x >> 5;
#pragma unroll
    for (int o = 16; o > 0; o >>= 1)
        v = fmaxf(v, __shfl_xor_sync(0xffffffffu, v, o));
    __syncthreads();
    if (lane == 0) s[wid] = v;
    __syncthreads();
    float r = s[0];
#pragma unroll
    for (int i = 1; i < 8; i++) r = fmaxf(r, s[i]);
    return r;
}

__device__ __forceinline__ float blockReduceSum(float v) {
    __shared__ float s[8];
    const int lane = threadIdx.x & 31, wid = threadIdx.x >> 5;
#pragma unroll
    for (int o = 16; o > 0; o >>= 1)
        v += __shfl_xor_sync(0xffffffffu, v, o);
    __syncthreads();
    if (lane == 0) s[wid] = v;
    __syncthreads();
    float r = s[0];
#pragma unroll
    for (int i = 1; i < 8; i++) r += s[i];
    return r;
}

// ---------------------------------------------------------------------------
// SGEMM  C[m,n] = sum_k A[m,k] * B[n,k]  (NT), tile 128x128, 8x8 microtile.
// Optional residual add (res uses ldc). Dims must be multiples of 128 / K of 8.
// ---------------------------------------------------------------------------
__global__ __launch_bounds__(256) void sgemm_nt_128x128(
    const float* __restrict__ A, const float* __restrict__ Bm,
    float* __restrict__ C, const float* __restrict__ res,
    int K, int lda, int ldb, int ldc)
{
    __shared__ __align__(16) float As[8][128];
    __shared__ __align__(16) float Bs[8][128];
    const int tid = threadIdx.x;
    const int tx = tid & 15;
    const int ty = tid >> 4;
    const int rowBase = blockIdx.y * 128;
    const int colBase = blockIdx.x * 128;
    const int lr = tid >> 1;
    const int lc = (tid & 1) * 4;

    const float* Ag = A + (size_t)(rowBase + lr) * lda + lc;
    const float* Bg = Bm + (size_t)(colBase + lr) * ldb + lc;

    float acc[8][8];
#pragma unroll
    for (int i = 0; i < 8; i++)
#pragma unroll
        for (int j = 0; j < 8; j++) acc[i][j] = 0.f;

    for (int k0 = 0; k0 < K; k0 += 8) {
        float4 av = *(const float4*)(Ag + k0);
        float4 bv = *(const float4*)(Bg + k0);
        As[lc + 0][lr] = av.x; As[lc + 1][lr] = av.y;
        As[lc + 2][lr] = av.z; As[lc + 3][lr] = av.w;
        Bs[lc + 0][lr] = bv.x; Bs[lc + 1][lr] = bv.y;
        Bs[lc + 2][lr] = bv.z; Bs[lc + 3][lr] = bv.w;
        __syncthreads();
#pragma unroll
        for (int k = 0; k < 8; ++k) {
            float4 a0 = *(const float4*)&As[k][ty * 4];
            float4 a1 = *(const float4*)&As[k][64 + ty * 4];
            float4 b0 = *(const float4*)&Bs[k][tx * 4];
            float4 b1 = *(const float4*)&Bs[k][64 + tx * 4];
            float ar[8] = {a0.x, a0.y, a0.z, a0.w, a1.x, a1.y, a1.z, a1.w};
            float br[8] = {b0.x, b0.y, b0.z, b0.w, b1.x, b1.y, b1.z, b1.w};
#pragma unroll
            for (int i = 0; i < 8; i++)
#pragma unroll
                for (int j = 0; j < 8; j++)
                    acc[i][j] = fmaf(ar[i], br[j], acc[i][j]);
        }
        __syncthreads();
    }
#pragma unroll
    for (int i = 0; i < 8; i++) {
        int r = rowBase + ((i < 4) ? ty * 4 + i : 64 + ty * 4 + (i - 4));
#pragma unroll
        for (int j = 0; j < 8; j++) {
            int c = colBase + ((j < 4) ? tx * 4 + j : 64 + tx * 4 + (j - 4));
            float v = acc[i][j];
            if (res) v += res[(size_t)r * ldc + c];
            C[(size_t)r * ldc + c] = v;
        }
    }
}

// ---------------------------------------------------------------------------
// scores[b,h,q,k] = (Q_h[q,:] . K_h[k,:]) / 8, masked to -1e9 where mask==0
// tile 128x128, K=64. grid = (S/128, S/128, B*NH)
// ---------------------------------------------------------------------------
__global__ __launch_bounds__(256) void scores_kernel(
    const float* __restrict__ Q, const float* __restrict__ Kmat,
    const int* __restrict__ mask, float* __restrict__ attn)
{
    const int bh = blockIdx.z;
    const int b = bh >> 4;
    const int h = bh & 15;
    __shared__ __align__(16) float As[8][128];
    __shared__ __align__(16) float Bs[8][128];
    const int tid = threadIdx.x;
    const int tx = tid & 15;
    const int ty = tid >> 4;
    const int rowBase = blockIdx.y * 128;
    const int colBase = blockIdx.x * 128;
    const int lr = tid >> 1;
    const int lc = (tid & 1) * 4;

    const size_t hoff = (size_t)b * S_ * HID + (size_t)h * DK;
    const float* Ag = Q + hoff + (size_t)(rowBase + lr) * HID + lc;
    const float* Bg = Kmat + hoff + (size_t)(colBase + lr) * HID + lc;

    float acc[8][8];
#pragma unroll
    for (int i = 0; i < 8; i++)
#pragma unroll
        for (int j = 0; j < 8; j++) acc[i][j] = 0.f;

    for (int k0 = 0; k0 < DK; k0 += 8) {
        float4 av = *(const float4*)(Ag + k0);
        float4 bv = *(const float4*)(Bg + k0);
        As[lc + 0][lr] = av.x; As[lc + 1][lr] = av.y;
        As[lc + 2][lr] = av.z; As[lc + 3][lr] = av.w;
        Bs[lc + 0][lr] = bv.x; Bs[lc + 1][lr] = bv.y;
        Bs[lc + 2][lr] = bv.z; Bs[lc + 3][lr] = bv.w;
        __syncthreads();
#pragma unroll
        for (int k = 0; k < 8; ++k) {
            float4 a0 = *(const float4*)&As[k][ty * 4];
            float4 a1 = *(const float4*)&As[k][64 + ty * 4];
            float4 b0 = *(const float4*)&Bs[k][tx * 4];
            float4 b1 = *(const float4*)&Bs[k][64 + tx * 4];
            float ar[8] = {a0.x, a0.y, a0.z, a0.w, a1.x, a1.y, a1.z, a1.w};
            float br[8] = {b0.x, b0.y, b0.z, b0.w, b1.x, b1.y, b1.z, b1.w};
#pragma unroll
            for (int i = 0; i < 8; i++)
#pragma unroll
                for (int j = 0; j < 8; j++)
                    acc[i][j] = fmaf(ar[i], br[j], acc[i][j]);
        }
        __syncthreads();
    }

    const int* mrow = mask + (size_t)b * S_ * S_;
    float* arow = attn + (size_t)bh * S_ * S_;
#pragma unroll
    for (int i = 0; i < 8; i++) {
        int r = rowBase + ((i < 4) ? ty * 4 + i : 64 + ty * 4 + (i - 4));
#pragma unroll
        for (int j = 0; j < 8; j++) {
            int c = colBase + ((j < 4) ? tx * 4 + j : 64 + tx * 4 + (j - 4));
            float v = acc[i][j] * 0.125f;   // 1/sqrt(64)
            int m = mrow[(size_t)r * S_ + c];
            arow[(size_t)r * S_ + c] = (m != 0) ? v : -1e9f;
        }
    }
}

// ---------------------------------------------------------------------------
// Row softmax over 2048 elements, in place. grid = B*NH*S rows, 256 threads.
// ---------------------------------------------------------------------------
__global__ __launch_bounds__(256) void softmax_kernel(float* __restrict__ attn)
{
    const size_t row = blockIdx.x;
    float4* p = (float4*)(attn + row * (size_t)S_);
    const int tid = threadIdx.x;
    float4 v0 = p[tid];
    float4 v1 = p[tid + 256];
    float m = fmaxf(fmaxf(fmaxf(v0.x, v0.y), fmaxf(v0.z, v0.w)),
                    fmaxf(fmaxf(v1.x, v1.y), fmaxf(v1.z, v1.w)));
    m = blockReduceMax(m);
    float4 e0, e1;
    e0.x = __expf(v0.x - m); e0.y = __expf(v0.y - m);
    e0.z = __expf(v0.z - m); e0.w = __expf(v0.w - m);
    e1.x = __expf(v1.x - m); e1.y = __expf(v1.y - m);
    e1.z = __expf(v1.z - m); e1.w = __expf(v1.w - m);
    float s = e0.x + e0.y + e0.z + e0.w + e1.x + e1.y + e1.z + e1.w;
    s = blockReduceSum(s);
    float inv = 1.0f / s;
    e0.x *= inv; e0.y *= inv; e0.z *= inv; e0.w *= inv;
    e1.x *= inv; e1.y *= inv; e1.z *= inv; e1.w *= inv;
    p[tid] = e0;
    p[tid + 256] = e1;
}

// ---------------------------------------------------------------------------
// context[q,d] = sum_k attn[q,k] * V[b*S+k, h*64+d]   (NN gemm, N=64)
// tile 128x64, K=S. grid = (1, S/128, B*NH)
// ---------------------------------------------------------------------------
__global__ __launch_bounds__(256) void context_kernel(
    const float* __restrict__ attn, const float* __restrict__ V)
{
    const int bh = blockIdx.z;
    const int b = bh >> 4;
    const int h = bh & 15;
    const int rowBase = blockIdx.y * 128;
    __shared__ __align__(16) float As[8][128];
    __shared__ __align__(16) float Bs[8][64];
    const int tid = threadIdx.x;
    const int tx = tid & 15;
    const int ty = tid >> 4;
    const int lr = tid >> 1;
    const int lc = (tid & 1) * 4;

    const float* Ag = attn + (size_t)bh * S_ * S_ + (size_t)(rowBase + lr) * S_ + lc;
    const float* Bp = V + (size_t)b * S_ * HID + (size_t)h * DK;

    float acc[8][4];
#pragma unroll
    for (int i = 0; i < 8; i++)
#pragma unroll
        for (int j = 0; j < 4; j++) acc[i][j] = 0.f;

    for (int k0 = 0; k0 < S_; k0 += 8) {
        float4 av = *(const float4*)(Ag + k0);
        As[lc + 0][lr] = av.x; As[lc + 1][lr] = av.y;
        As[lc + 2][lr] = av.z; As[lc + 3][lr] = av.w;
        if (tid < 128) {
            int kk = tid >> 4;          // 0..7
            int d4 = (tid & 15) * 4;    // 0..60
            float4 bv = *(const float4*)(Bp + (size_t)(k0 + kk) * HID + d4);
            Bs[kk][d4 + 0] = bv.x; Bs[kk][d4 + 1] = bv.y;
            Bs[kk][d4 + 2] = bv.z; Bs[kk][d4 + 3] = bv.w;
        }
        __syncthreads();
#pragma unroll
        for (int k = 0; k < 8; ++k) {
            float4 a0 = *(const float4*)&As[k][ty * 4];
            float4 a1 = *(const float4*)&As[k][64 + ty * 4];
            float4 b0 = *(const float4*)&Bs[k][tx * 4];
            float ar[8] = {a0.x, a0.y, a0.z, a0.w, a1.x, a1.y, a1.z, a1.w};
            float br[4] = {b0.x, b0.y, b0.z, b0.w};
#pragma unroll
            for (int i = 0; i < 8; i++)
#pragma unroll
                for (int j = 0; j < 4; j++)
                    acc[i][j] = fmaf(ar[i], br[j], acc[i][j]);
        }
        __syncthreads();
    }

    float* Cp = g_ctx + (size_t)b * S_ * HID + (size_t)h * DK;
#pragma unroll
    for (int i = 0; i < 8; i++) {
        int r = rowBase + ((i < 4) ? ty * 4 + i : 64 + ty * 4 + (i - 4));
#pragma unroll
        for (int j = 0; j < 4; j++)
            Cp[(size_t)r * HID + tx * 4 + j] = acc[i][j];
    }
}

// ---------------------------------------------------------------------------
// LayerNorm over HID=1024, weight=1, bias=0, eps=1e-5. grid = ROWS, 256 thr.
// ---------------------------------------------------------------------------
__global__ __launch_bounds__(256) void ln_kernel(
    const float* __restrict__ x, float* __restrict__ out)
{
    const size_t row = blockIdx.x;
    const float4* p = (const float4*)(x + row * HID);
    const int tid = threadIdx.x;
    float4 v = p[tid];
    float s = v.x + v.y + v.z + v.w;
    s = blockReduceSum(s);
    const float mu = s * (1.0f / HID);
    float dx = v.x - mu, dy = v.y - mu, dz = v.z - mu, dw = v.w - mu;
    float sq = dx * dx + dy * dy + dz * dz + dw * dw;
    sq = blockReduceSum(sq);
    const float inv = rsqrtf(sq * (1.0f / HID) + 1e-5f);
    float4 o;
    o.x = dx * inv; o.y = dy * inv; o.z = dz * inv; o.w = dw * inv;
    ((float4*)(out + row * HID))[tid] = o;
}

// ---------------------------------------------------------------------------
extern "C" void kernel_launch(void* const* d_in, const int* in_sizes, int n_in,
                              void* d_out, int out_size)
{
    (void)in_sizes; (void)n_in; (void)out_size;
    const float* x  = (const float*)d_in[0];
    const int* mask = (const int*)d_in[1];
    const float* Wq = (const float*)d_in[2];
    const float* Wk = (const float*)d_in[3];
    const float* Wv = (const float*)d_in[4];
    const float* Wo = (const float*)d_in[5];
    float* out  = (float*)d_out;
    float* attn = out + OUT_ELEMS;

    float *gQ, *gK, *gV, *gctx, *gtmp;
    cudaGetSymbolAddress((void**)&gQ,   g_Q);
    cudaGetSymbolAddress((void**)&gK,   g_K);
    cudaGetSymbolAddress((void**)&gV,   g_V);
    cudaGetSymbolAddress((void**)&gctx, g_ctx);
    cudaGetSymbolAddress((void**)&gtmp, g_tmp);

    dim3 blk(256);
    dim3 gProj(HID / 128, ROWS / 128);            // (8, 32)

    // Q/K/V projections: [4096,1024] = X @ W^T
    sgemm_nt_128x128<<<gProj, blk>>>(x, Wq, gQ, nullptr, HID, HID, HID, HID);
    sgemm_nt_128x128<<<gProj, blk>>>(x, Wk, gK, nullptr, HID, HID, HID, HID);
    sgemm_nt_128x128<<<gProj, blk>>>(x, Wv, gV, nullptr, HID, HID, HID, HID);

    // Masked scaled scores -> attn buffer (raw)
    scores_kernel<<<dim3(S_ / 128, S_ / 128, B_ * NH), blk>>>(gQ, gK, mask, attn);

    // Row softmax in place
    softmax_kernel<<<dim3(B_ * NH * S_), blk>>>(attn);

    // context = attn @ V_head
    context_kernel<<<dim3(1, S_ / 128, B_ * NH), blk>>>(attn, gV);

    // Output projection + residual
    sgemm_nt_128x128<<<gProj, blk>>>(gctx, Wo, gtmp, x, HID, HID, HID, HID);

    // LayerNorm -> final output
    ln_kernel<<<dim3(ROWS), blk>>>(gtmp, out);
}

// round 3
// speedup vs baseline: 1.6302x; 1.6302x over previous
#include <cuda_runtime.h>
#include <cuda_bf16.h>
#include <cstdint>
#include <math.h>

#define B_   2
#define S_   2048
#define NH   16
#define DK   64
#define HID  1024
#define ROWS (B_ * S_)          // 4096

static const size_t OUT_ELEMS = (size_t)ROWS * HID;   // 4,194,304

// Scratch (__device__ globals; no allocation allowed)
__device__ float g_Q [(size_t)ROWS * HID];
__device__ float g_K [(size_t)ROWS * HID];
__device__ float g_V [(size_t)ROWS * HID];
__device__ float g_Vt[(size_t)B_ * NH * DK * S_];     // [bh][d][k]
__device__ float g_ctx[(size_t)ROWS * HID];
__device__ float g_tmp[(size_t)ROWS * HID];

// ===========================================================================
// Warp-MMA helpers (sm_80-era PTX: valid on the compute_103 virtual target)
// ===========================================================================
__device__ __forceinline__ uint32_t smem_u32(const void* p) {
    uint32_t a;
    asm("{ .reg .u64 t; cvta.to.shared.u64 t, %1; cvt.u32.u64 %0, t; }"
        : "=r"(a) : "l"(p));
    return a;
}
__device__ __forceinline__ void ldsm_x4(uint32_t (&r)[4], uint32_t addr) {
    asm volatile("ldmatrix.sync.aligned.m8n8.x4.shared.b16 {%0,%1,%2,%3}, [%4];"
                 : "=r"(r[0]), "=r"(r[1]), "=r"(r[2]), "=r"(r[3]) : "r"(addr));
}
__device__ __forceinline__ void ldsm_x2(uint32_t (&r)[2], uint32_t addr) {
    asm volatile("ldmatrix.sync.aligned.m8n8.x2.shared.b16 {%0,%1}, [%2];"
                 : "=r"(r[0]), "=r"(r[1]) : "r"(addr));
}
__device__ __forceinline__ void mma16816(float (&c)[4], const uint32_t (&a)[4],
                                         const uint32_t (&b)[2]) {
    asm volatile(
        "mma.sync.aligned.m16n8k16.row.col.f32.bf16.bf16.f32 "
        "{%0,%1,%2,%3}, {%4,%5,%6,%7}, {%8,%9}, {%0,%1,%2,%3};"
        : "+f"(c[0]), "+f"(c[1]), "+f"(c[2]), "+f"(c[3])
        : "r"(a[0]), "r"(a[1]), "r"(a[2]), "r"(a[3]), "r"(b[0]), "r"(b[1]));
}

// 2-term bf16 split of a float pair, packed little-endian (elem0 = low half)
__device__ __forceinline__ void split2(float x, float y, uint32_t& hi, uint32_t& lo) {
    __nv_bfloat16 hx = __float2bfloat16(x);
    __nv_bfloat16 hy = __float2bfloat16(y);
    __nv_bfloat16 lx = __float2bfloat16(x - __bfloat162float(hx));
    __nv_bfloat16 ly = __float2bfloat16(y - __bfloat162float(hy));
    hi = (uint32_t)__bfloat16_as_ushort(hx) | ((uint32_t)__bfloat16_as_ushort(hy) << 16);
    lo = (uint32_t)__bfloat16_as_ushort(lx) | ((uint32_t)__bfloat16_as_ushort(ly) << 16);
}
// Store 4 source floats at tile (row, c..c+3): hi at cols c, lo at cols c+32.
// Tile row = 72 bf16 (144 B): 16B-aligned rows, conflict-free ldmatrix phases.
__device__ __forceinline__ void sts_f4(__nv_bfloat16 (*T)[72], int row, int c, float4 v) {
    uint32_t h0, l0, h1, l1;
    split2(v.x, v.y, h0, l0);
    split2(v.z, v.w, h1, l1);
    uint32_t* p = (uint32_t*)&T[row][c];
    p[0] = h0; p[1] = h1;
    uint32_t* q = (uint32_t*)&T[row][c + 32];
    q[0] = l0; q[1] = l1;
}

// One K-chunk (32 source floats = 2 k16 steps) of split-MMA for a warp tile
// 32 x (NT*8).  c layout: [mt(2)][nt(NT)][4].
template <int NT>
__device__ __forceinline__ void mma_chunk(float (*cacc)[NT][4],
                                          const __nv_bfloat16 (*As)[72],
                                          const __nv_bfloat16 (*Bs)[72],
                                          int wm, int wn, int lane) {
#pragma unroll
    for (int s = 0; s < 2; s++) {
        uint32_t ah[2][4], al[2][4];
#pragma unroll
        for (int mt = 0; mt < 2; mt++) {
            const int r = wm * 32 + mt * 16 + (lane & 15);
            const int cc = s * 16 + ((lane >> 4) << 3);
            ldsm_x4(ah[mt], smem_u32(&As[r][cc]));
            ldsm_x4(al[mt], smem_u32(&As[r][cc + 32]));
        }
#pragma unroll
        for (int nt = 0; nt < NT; nt++) {
            const int br = wn * (NT * 8) + nt * 8 + (lane & 7);
            const int bc = s * 16 + ((lane >> 3) & 1) * 8;
            uint32_t bh[2], bl[2];
            ldsm_x2(bh, smem_u32(&Bs[br][bc]));
            ldsm_x2(bl, smem_u32(&Bs[br][bc + 32]));
#pragma unroll
            for (int mt = 0; mt < 2; mt++) {
                mma16816(cacc[mt][nt], ah[mt], bh);   // hi*hi
                mma16816(cacc[mt][nt], ah[mt], bl);   // hi*lo
                mma16816(cacc[mt][nt], al[mt], bh);   // lo*hi
            }
        }
    }
}

// ===========================================================================
// Linear: C[128x128 tile] = A @ B^T (+res). K=1024. 8 warps, warp tile 32x64.
// ===========================================================================
__device__ __forceinline__ void lin_body(const float* __restrict__ A,
                                         const float* __restrict__ Bw,
                                         float* __restrict__ C,
                                         const float* __restrict__ res) {
    __shared__ __align__(16) __nv_bfloat16 As[128][72];
    __shared__ __align__(16) __nv_bfloat16 Bs[128][72];
    const int tid = threadIdx.x, lane = tid & 31, wid = tid >> 5;
    const int wm = wid & 3, wn = wid >> 2;
    const int rowBase = blockIdx.y * 128, colBase = blockIdx.x * 128;
    const int lr = tid >> 1, c0 = (tid & 1) * 16;
    const float* Ar = A + (size_t)(rowBase + lr) * HID + c0;
    const float* Br = Bw + (size_t)(colBase + lr) * HID + c0;

    float c[2][8][4] = {};
    float4 ra[4], rb[4];
#pragma unroll
    for (int i = 0; i < 4; i++) {
        ra[i] = *(const float4*)(Ar + i * 4);
        rb[i] = *(const float4*)(Br + i * 4);
    }
    for (int ch = 0; ch < 32; ch++) {
#pragma unroll
        for (int i = 0; i < 4; i++) {
            sts_f4(As, lr, c0 + i * 4, ra[i]);
            sts_f4(Bs, lr, c0 + i * 4, rb[i]);
        }
        __syncthreads();
        if (ch < 31) {
            const float* An = Ar + (ch + 1) * 32;
            const float* Bn = Br + (ch + 1) * 32;
#pragma unroll
            for (int i = 0; i < 4; i++) {
                ra[i] = *(const float4*)(An + i * 4);
                rb[i] = *(const float4*)(Bn + i * 4);
            }
        }
        mma_chunk<8>(c, As, Bs, wm, wn, lane);
        __syncthreads();
    }
#pragma unroll
    for (int mt = 0; mt < 2; mt++) {
        const int r0 = rowBase + wm * 32 + mt * 16 + (lane >> 2);
#pragma unroll
        for (int nt = 0; nt < 8; nt++) {
            const int cc = colBase + wn * 64 + nt * 8 + (lane & 3) * 2;
            float2 v0 = make_float2(c[mt][nt][0], c[mt][nt][1]);
            float2 v1 = make_float2(c[mt][nt][2], c[mt][nt][3]);
            if (res) {
                float2 q0 = *(const float2*)(res + (size_t)r0 * HID + cc);
                float2 q1 = *(const float2*)(res + (size_t)(r0 + 8) * HID + cc);
                v0.x += q0.x; v0.y += q0.y;
                v1.x += q1.x; v1.y += q1.y;
            }
            *(float2*)(C + (size_t)r0 * HID + cc) = v0;
            *(float2*)(C + (size_t)(r0 + 8) * HID + cc) = v1;
        }
    }
}

__global__ __launch_bounds__(256) void tc_proj_qkv(const float* __restrict__ X,
                                                   const float* __restrict__ Wq,
                                                   const float* __restrict__ Wk,
                                                   const float* __restrict__ Wv) {
    const int z = blockIdx.z;
    const float* W = (z == 0) ? Wq : (z == 1) ? Wk : Wv;
    float* C = (z == 0) ? g_Q : (z == 1) ? g_K : g_V;
    lin_body(X, W, C, nullptr);
}
__global__ __launch_bounds__(256) void tc_oproj(const float* __restrict__ Wo,
                                                const float* __restrict__ X) {
    lin_body(g_ctx, Wo, g_tmp, X);
}

// ===========================================================================
// Scores: attn_raw = (Q_h @ K_h^T)/8, masked -> -1e9.  grid (16,16,32)
// ===========================================================================
__global__ __launch_bounds__(256) void tc_scores(const int* __restrict__ mask,
                                                 float* __restrict__ attn) {
    __shared__ __align__(16) __nv_bfloat16 As[128][72];
    __shared__ __align__(16) __nv_bfloat16 Bs[128][72];
    const int tid = threadIdx.x, lane = tid & 31, wid = tid >> 5;
    const int wm = wid & 3, wn = wid >> 2;
    const int bh = blockIdx.z, b = bh >> 4, h = bh & 15;
    const int rowBase = blockIdx.y * 128, colBase = blockIdx.x * 128;
    const int lr = tid >> 1, c0 = (tid & 1) * 16;
    const size_t hoff = (size_t)b * S_ * HID + (size_t)h * DK;
    const float* Ar = g_Q + hoff + (size_t)(rowBase + lr) * HID + c0;
    const float* Br = g_K + hoff + (size_t)(colBase + lr) * HID + c0;

    float c[2][8][4] = {};
    float4 ra[4], rb[4];
#pragma unroll
    for (int i = 0; i < 4; i++) {
        ra[i] = *(const float4*)(Ar + i * 4);
        rb[i] = *(const float4*)(Br + i * 4);
    }
    for (int ch = 0; ch < 2; ch++) {          // K = 64
#pragma unroll
        for (int i = 0; i < 4; i++) {
            sts_f4(As, lr, c0 + i * 4, ra[i]);
            sts_f4(Bs, lr, c0 + i * 4, rb[i]);
        }
        __syncthreads();
        if (ch < 1) {
#pragma unroll
            for (int i = 0; i < 4; i++) {
                ra[i] = *(const float4*)(Ar + 32 + i * 4);
                rb[i] = *(const float4*)(Br + 32 + i * 4);
            }
        }
        mma_chunk<8>(c, As, Bs, wm, wn, lane);
        __syncthreads();
    }
    const int* mb = mask + (size_t)b * S_ * S_;
    float* ab = attn + (size_t)bh * S_ * S_;
#pragma unroll
    for (int mt = 0; mt < 2; mt++) {
        const int r0 = rowBase + wm * 32 + mt * 16 + (lane >> 2);
#pragma unroll
        for (int nt = 0; nt < 8; nt++) {
            const int cc = colBase + wn * 64 + nt * 8 + (lane & 3) * 2;
            int2 m0 = *(const int2*)(mb + (size_t)r0 * S_ + cc);
            int2 m1 = *(const int2*)(mb + (size_t)(r0 + 8) * S_ + cc);
            float2 v0, v1;
            v0.x = m0.x ? c[mt][nt][0] * 0.125f : -1e9f;
            v0.y = m0.y ? c[mt][nt][1] * 0.125f : -1e9f;
            v1.x = m1.x ? c[mt][nt][2] * 0.125f : -1e9f;
            v1.y = m1.y ? c[mt][nt][3] * 0.125f : -1e9f;
            *(float2*)(ab + (size_t)r0 * S_ + cc) = v0;
            *(float2*)(ab + (size_t)(r0 + 8) * S_ + cc) = v1;
        }
    }
}

// ===========================================================================
// Context: ctx[q,d] = sum_k attn[q,k] * Vt[bh][d][k].  N=64, warp tile 32x32.
// grid (16,1,32)
// ===========================================================================
__global__ __launch_bounds__(256) void tc_context(const float* __restrict__ attn) {
    __shared__ __align__(16) __nv_bfloat16 As[128][72];
    __shared__ __align__(16) __nv_bfloat16 Bs[64][72];
    const int tid = threadIdx.x, lane = tid & 31, wid = tid >> 5;
    const int wm = wid & 3, wn = wid >> 2;
    const int bh = blockIdx.z, b = bh >> 4, h = bh & 15;
    const int rowBase = blockIdx.x * 128;
    const int lr = tid >> 1, c0 = (tid & 1) * 16;       // A loader: 2 thr/row
    const int brow = tid >> 2, bc0 = (tid & 3) * 8;     // B loader: 4 thr/row
    const float* Ar = attn + (size_t)bh * S_ * S_ + (size_t)(rowBase + lr) * S_ + c0;
    const float* Br = g_Vt + (size_t)bh * DK * S_ + (size_t)brow * S_ + bc0;

    float c[2][4][4] = {};
    float4 ra[4], rb[2];
#pragma unroll
    for (int i = 0; i < 4; i++) ra[i] = *(const float4*)(Ar + i * 4);
    rb[0] = *(const float4*)(Br);
    rb[1] = *(const float4*)(Br + 4);
    for (int ch = 0; ch < 64; ch++) {         // K = 2048
#pragma unroll
        for (int i = 0; i < 4; i++) sts_f4(As, lr, c0 + i * 4, ra[i]);
        sts_f4(Bs, brow, bc0, rb[0]);
        sts_f4(Bs, brow, bc0 + 4, rb[1]);
        __syncthreads();
        if (ch < 63) {
            const float* An = Ar + (ch + 1) * 32;
            const float* Bn = Br + (ch + 1) * 32;
#pragma unroll
            for (int i = 0; i < 4; i++) ra[i] = *(const float4*)(An + i * 4);
            rb[0] = *(const float4*)(Bn);
            rb[1] = *(const float4*)(Bn + 4);
        }
        mma_chunk<4>(c, As, Bs, wm, wn, lane);
        __syncthreads();
    }
#pragma unroll
    for (int mt = 0; mt < 2; mt++) {
        const int q0 = rowBase + wm * 32 + mt * 16 + (lane >> 2);
#pragma unroll
        for (int nt = 0; nt < 4; nt++) {
            const int d = wn * 32 + nt * 8 + (lane & 3) * 2;
            float* p0 = g_ctx + ((size_t)b * S_ + q0) * HID + (size_t)h * DK + d;
            float* p1 = g_ctx + ((size_t)b * S_ + q0 + 8) * HID + (size_t)h * DK + d;
            *(float2*)p0 = make_float2(c[mt][nt][0], c[mt][nt][1]);
            *(float2*)p1 = make_float2(c[mt][nt][2], c[mt][nt][3]);
        }
    }
}

// ===========================================================================
// V transpose: g_Vt[bh][d][k] = g_V[(b*S+k)*HID + h*64 + d]
// ===========================================================================
__global__ void vtrans_kernel() {
    __shared__ float ts[32][33];
    const int bh = blockIdx.z, b = bh >> 4, h = bh & 15;
    const int k0 = blockIdx.x * 32, d0 = blockIdx.y * 32;
    const int tx = threadIdx.x, ty = threadIdx.y;
#pragma unroll
    for (int i = 0; i < 4; i++) {
        int k = k0 + ty + i * 8;
        ts[ty + i * 8][tx] = g_V[((size_t)b * S_ + k) * HID + (size_t)h * DK + d0 + tx];
    }
    __syncthreads();
#pragma unroll
    for (int i = 0; i < 4; i++) {
        int d = d0 + ty + i * 8;
        g_Vt[(size_t)bh * DK * S_ + (size_t)d * S_ + k0 + tx] = ts[tx][ty + i * 8];
    }
}

// ===========================================================================
// Softmax + LayerNorm (unchanged)
// ===========================================================================
__device__ __forceinline__ float blockReduceMax(float v) {
    __shared__ float s[8];
    const int lane = threadIdx.x & 31, wid = threadIdx.x >> 5;
#pragma unroll
    for (int o = 16; o > 0; o >>= 1) v = fmaxf(v, __shfl_xor_sync(0xffffffffu, v, o));
    __syncthreads();
    if (lane == 0) s[wid] = v;
    __syncthreads();
    float r = s[0];
#pragma unroll
    for (int i = 1; i < 8; i++) r = fmaxf(r, s[i]);
    return r;
}
__device__ __forceinline__ float blockReduceSum(float v) {
    __shared__ float s[8];
    const int lane = threadIdx.x & 31, wid = threadIdx.x >> 5;
#pragma unroll
    for (int o = 16; o > 0; o >>= 1) v += __shfl_xor_sync(0xffffffffu, v, o);
    __syncthreads();
    if (lane == 0) s[wid] = v;
    __syncthreads();
    float r = s[0];
#pragma unroll
    for (int i = 1; i < 8; i++) r += s[i];
    return r;
}

__global__ __launch_bounds__(256) void softmax_kernel(float* __restrict__ attn) {
    const size_t row = blockIdx.x;
    float4* p = (float4*)(attn + row * (size_t)S_);
    const int tid = threadIdx.x;
    float4 v0 = p[tid];
    float4 v1 = p[tid + 256];
    float m = fmaxf(fmaxf(fmaxf(v0.x, v0.y), fmaxf(v0.z, v0.w)),
                    fmaxf(fmaxf(v1.x, v1.y), fmaxf(v1.z, v1.w)));
    m = blockReduceMax(m);
    float4 e0, e1;
    e0.x = __expf(v0.x - m); e0.y = __expf(v0.y - m);
    e0.z = __expf(v0.z - m); e0.w = __expf(v0.w - m);
    e1.x = __expf(v1.x - m); e1.y = __expf(v1.y - m);
    e1.z = __expf(v1.z - m); e1.w = __expf(v1.w - m);
    float s = e0.x + e0.y + e0.z + e0.w + e1.x + e1.y + e1.z + e1.w;
    s = blockReduceSum(s);
    float inv = 1.0f / s;
    e0.x *= inv; e0.y *= inv; e0.z *= inv; e0.w *= inv;
    e1.x *= inv; e1.y *= inv; e1.z *= inv; e1.w *= inv;
    p[tid] = e0;
    p[tid + 256] = e1;
}

__global__ __launch_bounds__(256) void ln_kernel(const float* __restrict__ x,
                                                 float* __restrict__ out) {
    const size_t row = blockIdx.x;
    const float4* p = (const float4*)(x + row * HID);
    const int tid = threadIdx.x;
    float4 v = p[tid];
    float s = v.x + v.y + v.z + v.w;
    s = blockReduceSum(s);
    const float mu = s * (1.0f / HID);
    float dx = v.x - mu, dy = v.y - mu, dz = v.z - mu, dw = v.w - mu;
    float sq = dx * dx + dy * dy + dz * dz + dw * dw;
    sq = blockReduceSum(sq);
    const float inv = rsqrtf(sq * (1.0f / HID) + 1e-5f);
    float4 o;
    o.x = dx * inv; o.y = dy * inv; o.z = dz * inv; o.w = dw * inv;
    ((float4*)(out + row * HID))[tid] = o;
}

// ===========================================================================
extern "C" void kernel_launch(void* const* d_in, const int* in_sizes, int n_in,
                              void* d_out, int out_size)
{
    (void)in_sizes; (void)n_in; (void)out_size;
    const float* x  = (const float*)d_in[0];
    const int* mask = (const int*)d_in[1];
    const float* Wq = (const float*)d_in[2];
    const float* Wk = (const float*)d_in[3];
    const float* Wv = (const float*)d_in[4];
    const float* Wo = (const float*)d_in[5];
    float* out  = (float*)d_out;
    float* attn = out + OUT_ELEMS;

    float* gtmp;
    cudaGetSymbolAddress((void**)&gtmp, g_tmp);

    dim3 blk(256);

    // Q/K/V projections (split-bf16 HMMA), batched over z
    tc_proj_qkv<<<dim3(HID / 128, ROWS / 128, 3), blk>>>(x, Wq, Wk, Wv);

    // V -> Vt (K-major per head)
    vtrans_kernel<<<dim3(S_ / 32, DK / 32, B_ * NH), dim3(32, 8)>>>();

    // Masked scaled raw scores
    tc_scores<<<dim3(S_ / 128, S_ / 128, B_ * NH), blk>>>(mask, attn);

    // Row softmax in place
    softmax_kernel<<<dim3(B_ * NH * S_), blk>>>(attn);

    // context = attn @ V_head
    tc_context<<<dim3(S_ / 128, 1, B_ * NH), blk>>>(attn);

    // Output projection + residual
    tc_oproj<<<dim3(HID / 128, ROWS / 128), blk>>>(Wo, x);

    // LayerNorm -> final output
    ln_kernel<<<dim3(ROWS), blk>>>(gtmp, out);
}